// round 1
// baseline (speedup 1.0000x reference)
#include <cuda_runtime.h>
#include <math.h>

#define BSZ 4
#define LSEQ 4096
#define DM 512
#define NH 8
#define ED 64
#define RN 64
#define MTOT (BSZ*LSEQ)   // 16384

// ---------- scratch (static device allocations; no cudaMalloc allowed) ----------
__device__ float g_q   [MTOT*DM];
__device__ float g_k   [MTOT*DM];
__device__ float g_z   [MTOT*DM];
__device__ float g_skip[MTOT*DM];
__device__ float g_scores[BSZ*NH*RN*LSEQ];   // [bh][r][s]
__device__ float g_rv [BSZ*NH*RN*ED];        // router_V
__device__ float g_cos[LSEQ*32];
__device__ float g_sin[LSEQ*32];

// ---------- RoPE table: pos = 4095 - t, theta_j = 10000^(-j/32) ----------
__global__ void rope_table_kernel() {
    int idx = blockIdx.x * blockDim.x + threadIdx.x;
    if (idx >= LSEQ * 32) return;
    int t = idx >> 5, j = idx & 31;
    float theta = (float)pow(10000.0, -(double)j / 32.0);
    float ang = (float)(LSEQ - 1 - t) * theta;
    g_cos[idx] = cosf(ang);
    g_sin[idx] = sinf(ang);
}

// ---------- kernel 1: Y = x@W + b for {Wq, Wk, Wskip, Wz(silu)} ----------
// BM=64, BN=64, BK=16, 256 threads, 4x4 per thread
__global__ __launch_bounds__(256) void gemm_big_kernel(
    const float* __restrict__ X,
    const float* __restrict__ Wq, const float* __restrict__ bq,
    const float* __restrict__ Wk, const float* __restrict__ bk,
    const float* __restrict__ Ws, const float* __restrict__ bs,
    const float* __restrict__ Wz, const float* __restrict__ bz)
{
    const float* W; const float* bias; float* Y; int act = 0;
    switch (blockIdx.z) {
        case 0: W = Wq; bias = bq; Y = g_q;    break;
        case 1: W = Wk; bias = bk; Y = g_k;    break;
        case 2: W = Ws; bias = bs; Y = g_skip; break;
        default: W = Wz; bias = bz; Y = g_z; act = 1; break;
    }
    const int K = DM, N = DM;
    int m0 = blockIdx.y * 64, n0 = blockIdx.x * 64;
    __shared__ float As[16][64];   // [k][m]
    __shared__ float Bs[16][64];   // [k][n]
    int tid = threadIdx.x;
    int am  = tid >> 2, ak4 = (tid & 3) * 4;
    int bkr = tid >> 4, bn4 = (tid & 15) * 4;
    int ty = tid >> 4, tx = tid & 15;
    float acc[4][4] = {};
    for (int k0 = 0; k0 < K; k0 += 16) {
        float4 av = *reinterpret_cast<const float4*>(&X[(size_t)(m0 + am) * K + k0 + ak4]);
        As[ak4 + 0][am] = av.x; As[ak4 + 1][am] = av.y;
        As[ak4 + 2][am] = av.z; As[ak4 + 3][am] = av.w;
        *reinterpret_cast<float4*>(&Bs[bkr][bn4]) =
            *reinterpret_cast<const float4*>(&W[(size_t)(k0 + bkr) * N + n0 + bn4]);
        __syncthreads();
        #pragma unroll
        for (int k = 0; k < 16; k++) {
            float4 a4 = *reinterpret_cast<const float4*>(&As[k][ty * 4]);
            float4 b4 = *reinterpret_cast<const float4*>(&Bs[k][tx * 4]);
            float a[4] = {a4.x, a4.y, a4.z, a4.w};
            float b[4] = {b4.x, b4.y, b4.z, b4.w};
            #pragma unroll
            for (int i = 0; i < 4; i++)
                #pragma unroll
                for (int j = 0; j < 4; j++)
                    acc[i][j] = fmaf(a[i], b[j], acc[i][j]);
        }
        __syncthreads();
    }
    #pragma unroll
    for (int i = 0; i < 4; i++) {
        #pragma unroll
        for (int j = 0; j < 4; j++) {
            int n = n0 + tx * 4 + j;
            float v = acc[i][j] + bias[n];
            if (act) v = v / (1.0f + expf(-v));   // silu
            Y[(size_t)(m0 + ty * 4 + i) * N + n] = v;
        }
    }
}

// ---------- kernel 2a: scores[bh][r][s] = 0.125 * sum_e r[h,r,e] * k[b,s,h,e] ----------
__global__ __launch_bounds__(256) void router_scores_kernel(const float* __restrict__ rp)
{
    int st = blockIdx.x * 64;
    int h = blockIdx.y, b = blockIdx.z;
    __shared__ float Rs[64][65];
    __shared__ float Ks[64][65];
    int tid = threadIdx.x;
    {
        int r = tid >> 2, e0 = (tid & 3) << 4;
        const float* src = rp + (size_t)r * DM + h * ED + e0;
        #pragma unroll
        for (int t = 0; t < 4; t++) {
            float4 v = *reinterpret_cast<const float4*>(src + 4 * t);
            Rs[r][e0 + 4*t] = v.x; Rs[r][e0 + 4*t + 1] = v.y;
            Rs[r][e0 + 4*t + 2] = v.z; Rs[r][e0 + 4*t + 3] = v.w;
        }
        const float* ksrc = g_k + (size_t)(b * LSEQ + st + r) * DM + h * ED + e0;
        #pragma unroll
        for (int t = 0; t < 4; t++) {
            float4 v = *reinterpret_cast<const float4*>(ksrc + 4 * t);
            Ks[r][e0 + 4*t] = v.x; Ks[r][e0 + 4*t + 1] = v.y;
            Ks[r][e0 + 4*t + 2] = v.z; Ks[r][e0 + 4*t + 3] = v.w;
        }
    }
    __syncthreads();
    int ty = tid >> 4, tx = tid & 15;
    float acc[4][4] = {};
    #pragma unroll 8
    for (int e = 0; e < 64; e++) {
        float a[4], bb[4];
        #pragma unroll
        for (int i = 0; i < 4; i++) a[i]  = Rs[ty * 4 + i][e];
        #pragma unroll
        for (int j = 0; j < 4; j++) bb[j] = Ks[tx * 4 + j][e];
        #pragma unroll
        for (int i = 0; i < 4; i++)
            #pragma unroll
            for (int j = 0; j < 4; j++)
                acc[i][j] = fmaf(a[i], bb[j], acc[i][j]);
    }
    size_t base = ((size_t)(b * NH + h) * RN) * LSEQ;
    #pragma unroll
    for (int i = 0; i < 4; i++)
        #pragma unroll
        for (int j = 0; j < 4; j++)
            g_scores[base + (size_t)(ty * 4 + i) * LSEQ + st + tx * 4 + j] = 0.125f * acc[i][j];
}

// ---------- kernel 2b: softmax over S (4096) per row ----------
__global__ __launch_bounds__(256) void softmax_rows_kernel()
{
    float* row = g_scores + (size_t)blockIdx.x * LSEQ;
    __shared__ float red[8];
    __shared__ float red2[8];
    int tid = threadIdx.x;
    float m = -1e30f;
    for (int i = tid; i < LSEQ; i += 256) m = fmaxf(m, row[i]);
    #pragma unroll
    for (int o = 16; o; o >>= 1) m = fmaxf(m, __shfl_xor_sync(~0u, m, o));
    if ((tid & 31) == 0) red[tid >> 5] = m;
    __syncthreads();
    float mall = red[0];
    #pragma unroll
    for (int t = 1; t < 8; t++) mall = fmaxf(mall, red[t]);
    float s = 0.0f;
    for (int i = tid; i < LSEQ; i += 256) {
        float e = expf(row[i] - mall);
        row[i] = e;
        s += e;
    }
    #pragma unroll
    for (int o = 16; o; o >>= 1) s += __shfl_xor_sync(~0u, s, o);
    if ((tid & 31) == 0) red2[tid >> 5] = s;
    __syncthreads();
    float Z = 0.0f;
    #pragma unroll
    for (int t = 0; t < 8; t++) Z += red2[t];
    float inv = 1.0f / Z;
    for (int i = tid; i < LSEQ; i += 256) row[i] *= inv;
}

__global__ void zero_rv_kernel()
{
    int idx = blockIdx.x * blockDim.x + threadIdx.x;
    if (idx < BSZ * NH * RN * ED) g_rv[idx] = 0.0f;
}

// ---------- kernel 2c: router_V = rope(A) @ v, K-split over S with atomics ----------
__global__ __launch_bounds__(256) void router_v_kernel(const float* __restrict__ X)
{
    int h = blockIdx.y, b = blockIdx.z;
    int s0 = blockIdx.x * 256;
    __shared__ float As[64][17];  // roped A': [r][s-sub]
    __shared__ float Vs[16][65];  // v: [s-sub][e]
    int tid = threadIdx.x;
    int ty = tid >> 4, tx = tid & 15;
    float acc[4][4] = {};
    size_t sbase = ((size_t)(b * NH + h) * RN) * LSEQ;
    for (int ss = 0; ss < 256; ss += 16) {
        int sb = s0 + ss;
        #pragma unroll
        for (int q = 0; q < 2; q++) {
            int pi = tid * 2 + q;          // 0..511 pairs: 32 j x 16 s
            int j = pi & 31, sl = pi >> 5;
            int s = sb + sl;
            float a0 = g_scores[sbase + (size_t)(2 * j) * LSEQ + s];
            float a1 = g_scores[sbase + (size_t)(2 * j + 1) * LSEQ + s];
            float c = g_cos[s * 32 + j], sn = g_sin[s * 32 + j];
            As[2 * j][sl]     = a0 * c - a1 * sn;
            As[2 * j + 1][sl] = a0 * sn + a1 * c;
        }
        {
            int sl = tid >> 4, e = (tid & 15) * 4;
            float4 v = *reinterpret_cast<const float4*>(
                &X[(size_t)(b * LSEQ + sb + sl) * DM + h * ED + e]);
            Vs[sl][e] = v.x; Vs[sl][e + 1] = v.y; Vs[sl][e + 2] = v.z; Vs[sl][e + 3] = v.w;
        }
        __syncthreads();
        #pragma unroll
        for (int s = 0; s < 16; s++) {
            float a[4], bb[4];
            #pragma unroll
            for (int i = 0; i < 4; i++) a[i]  = As[ty * 4 + i][s];
            #pragma unroll
            for (int j = 0; j < 4; j++) bb[j] = Vs[s][tx * 4 + j];
            #pragma unroll
            for (int i = 0; i < 4; i++)
                #pragma unroll
                for (int j = 0; j < 4; j++)
                    acc[i][j] = fmaf(a[i], bb[j], acc[i][j]);
        }
        __syncthreads();
    }
    size_t rvb = (size_t)(b * NH + h) * RN * ED;
    #pragma unroll
    for (int i = 0; i < 4; i++)
        #pragma unroll
        for (int j = 0; j < 4; j++)
            atomicAdd(&g_rv[rvb + (size_t)(ty * 4 + i) * ED + tx * 4 + j], acc[i][j]);
}

// ---------- kernel 3: q-branch attention + epilogue ----------
// per block: 32 tokens x 1 head
__global__ __launch_bounds__(256) void qattn_kernel(
    const float* __restrict__ rp, float* __restrict__ out)
{
    int b = blockIdx.z, h = blockIdx.y;
    int l0 = blockIdx.x * 32;
    __shared__ float Rh[64][66];   // router vectors, then router_V
    __shared__ float Qs[32][66];
    __shared__ float Ss[32][66];
    int tid = threadIdx.x;
    {   // load Rh (64x64)
        int r = tid >> 2, e0 = (tid & 3) << 4;
        const float* src = rp + (size_t)r * DM + h * ED + e0;
        #pragma unroll
        for (int t = 0; t < 4; t++) {
            float4 v = *reinterpret_cast<const float4*>(src + 4 * t);
            Rh[r][e0 + 4*t] = v.x; Rh[r][e0 + 4*t + 1] = v.y;
            Rh[r][e0 + 4*t + 2] = v.z; Rh[r][e0 + 4*t + 3] = v.w;
        }
    }
    {   // load Qs (32x64)
        int l = tid >> 3, e0 = (tid & 7) << 3;
        const float* src = g_q + (size_t)(b * LSEQ + l0 + l) * DM + h * ED + e0;
        #pragma unroll
        for (int t = 0; t < 2; t++) {
            float4 v = *reinterpret_cast<const float4*>(src + 4 * t);
            Qs[l][e0 + 4*t] = v.x; Qs[l][e0 + 4*t + 1] = v.y;
            Qs[l][e0 + 4*t + 2] = v.z; Qs[l][e0 + 4*t + 3] = v.w;
        }
    }
    __syncthreads();
    int ty = tid >> 4, tx = tid & 15;
    {   // q_scores = 0.125 * q @ r^T : 32x64, K=64
        float acc[2][4] = {};
        #pragma unroll 8
        for (int e = 0; e < 64; e++) {
            float a0 = Qs[ty * 2][e], a1 = Qs[ty * 2 + 1][e];
            float bb[4];
            #pragma unroll
            for (int j = 0; j < 4; j++) bb[j] = Rh[tx * 4 + j][e];
            #pragma unroll
            for (int j = 0; j < 4; j++) {
                acc[0][j] = fmaf(a0, bb[j], acc[0][j]);
                acc[1][j] = fmaf(a1, bb[j], acc[1][j]);
            }
        }
        #pragma unroll
        for (int i = 0; i < 2; i++)
            #pragma unroll
            for (int j = 0; j < 4; j++)
                Ss[ty * 2 + i][tx * 4 + j] = 0.125f * acc[i][j];
    }
    __syncthreads();
    {   // softmax over r (64) + RoPE, 8 threads per token row
        int l = tid >> 3, sub = tid & 7;
        int lt = l0 + l;
        float m = -1e30f;
        float v[8];
        #pragma unroll
        for (int t = 0; t < 8; t++) { v[t] = Ss[l][sub * 8 + t]; m = fmaxf(m, v[t]); }
        m = fmaxf(m, __shfl_xor_sync(~0u, m, 1));
        m = fmaxf(m, __shfl_xor_sync(~0u, m, 2));
        m = fmaxf(m, __shfl_xor_sync(~0u, m, 4));
        float zs = 0.0f;
        #pragma unroll
        for (int t = 0; t < 8; t++) { v[t] = expf(v[t] - m); zs += v[t]; }
        zs += __shfl_xor_sync(~0u, zs, 1);
        zs += __shfl_xor_sync(~0u, zs, 2);
        zs += __shfl_xor_sync(~0u, zs, 4);
        float inv = 1.0f / zs;
        #pragma unroll
        for (int t = 0; t < 8; t += 2) {
            int r = sub * 8 + t;
            int j = r >> 1;
            float c = g_cos[lt * 32 + j], sn = g_sin[lt * 32 + j];
            float a0 = v[t] * inv, a1 = v[t + 1] * inv;
            Ss[l][r]     = a0 * c - a1 * sn;
            Ss[l][r + 1] = a0 * sn + a1 * c;
        }
    }
    __syncthreads();
    {   // reload Rh <- router_V[b,h]
        int r = tid >> 2, e0 = (tid & 3) << 4;
        const float* src = g_rv + (size_t)(b * NH + h) * RN * ED + (size_t)r * ED + e0;
        #pragma unroll
        for (int t = 0; t < 4; t++) {
            float4 v = *reinterpret_cast<const float4*>(src + 4 * t);
            Rh[r][e0 + 4*t] = v.x; Rh[r][e0 + 4*t + 1] = v.y;
            Rh[r][e0 + 4*t + 2] = v.z; Rh[r][e0 + 4*t + 3] = v.w;
        }
    }
    __syncthreads();
    {   // V = A' @ router_V : 32x64, K=64; epilogue (V + skip) * z
        float acc[2][4] = {};
        #pragma unroll 8
        for (int r = 0; r < 64; r++) {
            float a0 = Ss[ty * 2][r], a1 = Ss[ty * 2 + 1][r];
            float bb[4];
            #pragma unroll
            for (int j = 0; j < 4; j++) bb[j] = Rh[r][tx * 4 + j];
            #pragma unroll
            for (int j = 0; j < 4; j++) {
                acc[0][j] = fmaf(a0, bb[j], acc[0][j]);
                acc[1][j] = fmaf(a1, bb[j], acc[1][j]);
            }
        }
        #pragma unroll
        for (int i = 0; i < 2; i++) {
            #pragma unroll
            for (int j = 0; j < 4; j++) {
                int l = ty * 2 + i, e = tx * 4 + j;
                size_t idx = (size_t)(b * LSEQ + l0 + l) * DM + h * ED + e;
                out[idx] = (acc[i][j] + g_skip[idx]) * g_z[idx];
            }
        }
    }
}

extern "C" void kernel_launch(void* const* d_in, const int* in_sizes, int n_in,
                              void* d_out, int out_size)
{
    const float* x     = (const float*)d_in[0];
    const float* Wq    = (const float*)d_in[1];
    const float* bq    = (const float*)d_in[2];
    const float* Wk    = (const float*)d_in[3];
    const float* bk    = (const float*)d_in[4];
    const float* Wskip = (const float*)d_in[5];
    const float* bskip = (const float*)d_in[6];
    const float* Wz    = (const float*)d_in[7];
    const float* bz    = (const float*)d_in[8];
    const float* rp    = (const float*)d_in[9];
    float* out = (float*)d_out;

    rope_table_kernel<<<(LSEQ * 32 + 255) / 256, 256>>>();
    gemm_big_kernel<<<dim3(DM / 64, MTOT / 64, 4), 256>>>(
        x, Wq, bq, Wk, bk, Wskip, bskip, Wz, bz);
    router_scores_kernel<<<dim3(LSEQ / 64, NH, BSZ), 256>>>(rp);
    softmax_rows_kernel<<<BSZ * NH * RN, 256>>>();
    zero_rv_kernel<<<(BSZ * NH * RN * ED + 255) / 256, 256>>>();
    router_v_kernel<<<dim3(LSEQ / 256, NH, BSZ), 256>>>(x);
    qattn_kernel<<<dim3(LSEQ / 32, NH, BSZ), 256>>>(rp, out);
}

// round 2
// speedup vs baseline: 1.5050x; 1.5050x over previous
#include <cuda_runtime.h>
#include <cuda_bf16.h>
#include <math.h>
#include <stdint.h>

#define BSZ 4
#define LSEQ 4096
#define DM 512
#define NH 8
#define ED 64
#define RN 64
#define MTOT (BSZ*LSEQ)   // 16384

// ---------- scratch ----------
__device__ float g_q   [MTOT*DM];
__device__ float g_k   [MTOT*DM];
__device__ float g_z   [MTOT*DM];
__device__ float g_skip[MTOT*DM];
__device__ float g_scores[BSZ*NH*RN*LSEQ];   // [bh][r][s]
__device__ float g_rv [BSZ*NH*RN*ED];        // router_V
__device__ float g_cos[LSEQ*32];
__device__ float g_sin[LSEQ*32];

// ---------- RoPE table ----------
__global__ void rope_table_kernel() {
    int idx = blockIdx.x * blockDim.x + threadIdx.x;
    if (idx >= LSEQ * 32) return;
    int t = idx >> 5, j = idx & 31;
    float theta = (float)pow(10000.0, -(double)j / 32.0);
    float ang = (float)(LSEQ - 1 - t) * theta;
    g_cos[idx] = cosf(ang);
    g_sin[idx] = sinf(ang);
}

// ---------- bf16 mma helper ----------
__device__ __forceinline__ void mma_bf16(float* c,
    uint32_t a0, uint32_t a1, uint32_t a2, uint32_t a3,
    uint32_t b0, uint32_t b1)
{
    asm volatile(
        "mma.sync.aligned.m16n8k16.row.col.f32.bf16.bf16.f32 "
        "{%0,%1,%2,%3},{%4,%5,%6,%7},{%8,%9},{%0,%1,%2,%3};"
        : "+f"(c[0]), "+f"(c[1]), "+f"(c[2]), "+f"(c[3])
        : "r"(a0), "r"(a1), "r"(a2), "r"(a3), "r"(b0), "r"(b1));
}

__device__ __forceinline__ void split_pack(float f0, float f1,
                                           uint32_t& hi, uint32_t& lo)
{
    __nv_bfloat16 h0 = __float2bfloat16(f0);
    __nv_bfloat16 h1 = __float2bfloat16(f1);
    __nv_bfloat16 l0 = __float2bfloat16(f0 - __bfloat162float(h0));
    __nv_bfloat16 l1 = __float2bfloat16(f1 - __bfloat162float(h1));
    __nv_bfloat162 hv = __halves2bfloat162(h0, h1);
    __nv_bfloat162 lv = __halves2bfloat162(l0, l1);
    hi = *reinterpret_cast<uint32_t*>(&hv);
    lo = *reinterpret_cast<uint32_t*>(&lv);
}

// ---------- kernel 1: tensor-core GEMM, Y = x@W + b (silu for z) ----------
// BM=128, BN=64, BK=32, 256 threads (8 warps: 4M x 2N), warp tile 32x32
// 3-term bf16 split: Ahi*Bhi + Ahi*Blo + Alo*Bhi  (~fp32 accuracy)
__global__ __launch_bounds__(256) void gemm_big_tc_kernel(
    const float* __restrict__ X,
    const float* __restrict__ Wq, const float* __restrict__ bq,
    const float* __restrict__ Wk, const float* __restrict__ bk,
    const float* __restrict__ Ws, const float* __restrict__ bs,
    const float* __restrict__ Wz, const float* __restrict__ bz)
{
    const float* W; const float* bias; float* Y; int act = 0;
    switch (blockIdx.z) {
        case 0: W = Wq; bias = bq; Y = g_q;    break;
        case 1: W = Wk; bias = bk; Y = g_k;    break;
        case 2: W = Ws; bias = bs; Y = g_skip; break;
        default: W = Wz; bias = bz; Y = g_z; act = 1; break;
    }
    const int m0 = blockIdx.y * 128;
    const int n0 = blockIdx.x * 64;

    // u32 = packed bf16x2 (k-pair). Rows padded to 17 words.
    __shared__ uint32_t sAh[128][17];
    __shared__ uint32_t sAl[128][17];
    __shared__ uint32_t sBh[64][17];
    __shared__ uint32_t sBl[64][17];

    const int tid  = threadIdx.x;
    const int warp = tid >> 5;
    const int lane = tid & 31;
    const int warpM = warp >> 1;    // 0..3
    const int warpN = warp & 1;     // 0..1
    const int gid = lane >> 2;      // 0..7
    const int lq  = lane & 3;       // 0..3

    // A loader mapping: row = tid>>1 (0..127), 16 floats at koff=(tid&1)*16
    const int a_row  = tid >> 1;
    const int a_koff = (tid & 1) * 16;
    // B loader mapping: n = tid&63, 8 k's starting at (tid>>6)*8
    const int b_n  = tid & 63;
    const int b_kb = (tid >> 6) * 8;

    float acc[2][4][4];
    #pragma unroll
    for (int i = 0; i < 2; i++)
        #pragma unroll
        for (int j = 0; j < 4; j++)
            #pragma unroll
            for (int q = 0; q < 4; q++) acc[i][j][q] = 0.0f;

    for (int k0 = 0; k0 < DM; k0 += 32) {
        // ---- load A tile 128x32 ----
        {
            const float* src = X + (size_t)(m0 + a_row) * DM + k0 + a_koff;
            #pragma unroll
            for (int t = 0; t < 4; t++) {
                float4 f = *reinterpret_cast<const float4*>(src + 4 * t);
                int c = (a_koff >> 1) + 2 * t;
                uint32_t hi, lo;
                split_pack(f.x, f.y, hi, lo);
                sAh[a_row][c] = hi; sAl[a_row][c] = lo;
                split_pack(f.z, f.w, hi, lo);
                sAh[a_row][c + 1] = hi; sAl[a_row][c + 1] = lo;
            }
        }
        // ---- load B tile (transposed to [n][k]) 64x32 ----
        {
            #pragma unroll
            for (int i = 0; i < 4; i++) {
                int kk = b_kb + 2 * i;
                float f0 = W[(size_t)(k0 + kk)     * DM + n0 + b_n];
                float f1 = W[(size_t)(k0 + kk + 1) * DM + n0 + b_n];
                uint32_t hi, lo;
                split_pack(f0, f1, hi, lo);
                sBh[b_n][kk >> 1] = hi;
                sBl[b_n][kk >> 1] = lo;
            }
        }
        __syncthreads();

        #pragma unroll
        for (int ks = 0; ks < 2; ks++) {
            const int c0 = ks * 8 + lq;
            // B fragments for 4 n-tiles
            uint32_t bh[4][2], bl[4][2];
            #pragma unroll
            for (int nt = 0; nt < 4; nt++) {
                int brow = warpN * 32 + nt * 8 + gid;
                bh[nt][0] = sBh[brow][c0];     bh[nt][1] = sBh[brow][c0 + 4];
                bl[nt][0] = sBl[brow][c0];     bl[nt][1] = sBl[brow][c0 + 4];
            }
            #pragma unroll
            for (int mt = 0; mt < 2; mt++) {
                int arow = warpM * 32 + mt * 16 + gid;
                uint32_t ah0 = sAh[arow][c0],     ah1 = sAh[arow + 8][c0];
                uint32_t ah2 = sAh[arow][c0 + 4], ah3 = sAh[arow + 8][c0 + 4];
                uint32_t al0 = sAl[arow][c0],     al1 = sAl[arow + 8][c0];
                uint32_t al2 = sAl[arow][c0 + 4], al3 = sAl[arow + 8][c0 + 4];
                #pragma unroll
                for (int nt = 0; nt < 4; nt++) {
                    mma_bf16(acc[mt][nt], ah0, ah1, ah2, ah3, bh[nt][0], bh[nt][1]);
                    mma_bf16(acc[mt][nt], ah0, ah1, ah2, ah3, bl[nt][0], bl[nt][1]);
                    mma_bf16(acc[mt][nt], al0, al1, al2, al3, bh[nt][0], bh[nt][1]);
                }
            }
        }
        __syncthreads();
    }

    // ---- epilogue: bias (+silu), store ----
    #pragma unroll
    for (int mt = 0; mt < 2; mt++) {
        int row0 = m0 + warpM * 32 + mt * 16 + gid;
        #pragma unroll
        for (int nt = 0; nt < 4; nt++) {
            int ncol = n0 + warpN * 32 + nt * 8 + lq * 2;
            float b0 = bias[ncol], b1 = bias[ncol + 1];
            float v0 = acc[mt][nt][0] + b0;
            float v1 = acc[mt][nt][1] + b1;
            float v2 = acc[mt][nt][2] + b0;
            float v3 = acc[mt][nt][3] + b1;
            if (act) {
                v0 = v0 / (1.0f + expf(-v0));
                v1 = v1 / (1.0f + expf(-v1));
                v2 = v2 / (1.0f + expf(-v2));
                v3 = v3 / (1.0f + expf(-v3));
            }
            *reinterpret_cast<float2*>(&Y[(size_t)row0 * DM + ncol])       = make_float2(v0, v1);
            *reinterpret_cast<float2*>(&Y[(size_t)(row0 + 8) * DM + ncol]) = make_float2(v2, v3);
        }
    }
}

// ---------- kernel 2a: scores[bh][r][s] ----------
__global__ __launch_bounds__(256) void router_scores_kernel(const float* __restrict__ rp)
{
    int st = blockIdx.x * 64;
    int h = blockIdx.y, b = blockIdx.z;
    __shared__ float Rs[64][65];
    __shared__ float Ks[64][65];
    int tid = threadIdx.x;
    {
        int r = tid >> 2, e0 = (tid & 3) << 4;
        const float* src = rp + (size_t)r * DM + h * ED + e0;
        #pragma unroll
        for (int t = 0; t < 4; t++) {
            float4 v = *reinterpret_cast<const float4*>(src + 4 * t);
            Rs[r][e0 + 4*t] = v.x; Rs[r][e0 + 4*t + 1] = v.y;
            Rs[r][e0 + 4*t + 2] = v.z; Rs[r][e0 + 4*t + 3] = v.w;
        }
        const float* ksrc = g_k + (size_t)(b * LSEQ + st + r) * DM + h * ED + e0;
        #pragma unroll
        for (int t = 0; t < 4; t++) {
            float4 v = *reinterpret_cast<const float4*>(ksrc + 4 * t);
            Ks[r][e0 + 4*t] = v.x; Ks[r][e0 + 4*t + 1] = v.y;
            Ks[r][e0 + 4*t + 2] = v.z; Ks[r][e0 + 4*t + 3] = v.w;
        }
    }
    __syncthreads();
    int ty = tid >> 4, tx = tid & 15;
    float acc[4][4] = {};
    #pragma unroll 8
    for (int e = 0; e < 64; e++) {
        float a[4], bb[4];
        #pragma unroll
        for (int i = 0; i < 4; i++) a[i]  = Rs[ty * 4 + i][e];
        #pragma unroll
        for (int j = 0; j < 4; j++) bb[j] = Ks[tx * 4 + j][e];
        #pragma unroll
        for (int i = 0; i < 4; i++)
            #pragma unroll
            for (int j = 0; j < 4; j++)
                acc[i][j] = fmaf(a[i], bb[j], acc[i][j]);
    }
    size_t base = ((size_t)(b * NH + h) * RN) * LSEQ;
    #pragma unroll
    for (int i = 0; i < 4; i++)
        #pragma unroll
        for (int j = 0; j < 4; j++)
            g_scores[base + (size_t)(ty * 4 + i) * LSEQ + st + tx * 4 + j] = 0.125f * acc[i][j];
}

// ---------- kernel 2b: softmax over S ----------
__global__ __launch_bounds__(256) void softmax_rows_kernel()
{
    float* row = g_scores + (size_t)blockIdx.x * LSEQ;
    __shared__ float red[8];
    __shared__ float red2[8];
    int tid = threadIdx.x;
    float m = -1e30f;
    for (int i = tid; i < LSEQ; i += 256) m = fmaxf(m, row[i]);
    #pragma unroll
    for (int o = 16; o; o >>= 1) m = fmaxf(m, __shfl_xor_sync(~0u, m, o));
    if ((tid & 31) == 0) red[tid >> 5] = m;
    __syncthreads();
    float mall = red[0];
    #pragma unroll
    for (int t = 1; t < 8; t++) mall = fmaxf(mall, red[t]);
    float s = 0.0f;
    for (int i = tid; i < LSEQ; i += 256) {
        float e = expf(row[i] - mall);
        row[i] = e;
        s += e;
    }
    #pragma unroll
    for (int o = 16; o; o >>= 1) s += __shfl_xor_sync(~0u, s, o);
    if ((tid & 31) == 0) red2[tid >> 5] = s;
    __syncthreads();
    float Z = 0.0f;
    #pragma unroll
    for (int t = 0; t < 8; t++) Z += red2[t];
    float inv = 1.0f / Z;
    for (int i = tid; i < LSEQ; i += 256) row[i] *= inv;
}

__global__ void zero_rv_kernel()
{
    int idx = blockIdx.x * blockDim.x + threadIdx.x;
    if (idx < BSZ * NH * RN * ED) g_rv[idx] = 0.0f;
}

// ---------- kernel 2c: router_V = rope(A) @ v ----------
__global__ __launch_bounds__(256) void router_v_kernel(const float* __restrict__ X)
{
    int h = blockIdx.y, b = blockIdx.z;
    int s0 = blockIdx.x * 256;
    __shared__ float As[64][17];
    __shared__ float Vs[16][65];
    int tid = threadIdx.x;
    int ty = tid >> 4, tx = tid & 15;
    float acc[4][4] = {};
    size_t sbase = ((size_t)(b * NH + h) * RN) * LSEQ;
    for (int ss = 0; ss < 256; ss += 16) {
        int sb = s0 + ss;
        #pragma unroll
        for (int q = 0; q < 2; q++) {
            int pi = tid * 2 + q;
            int j = pi & 31, sl = pi >> 5;
            int s = sb + sl;
            float a0 = g_scores[sbase + (size_t)(2 * j) * LSEQ + s];
            float a1 = g_scores[sbase + (size_t)(2 * j + 1) * LSEQ + s];
            float c = g_cos[s * 32 + j], sn = g_sin[s * 32 + j];
            As[2 * j][sl]     = a0 * c - a1 * sn;
            As[2 * j + 1][sl] = a0 * sn + a1 * c;
        }
        {
            int sl = tid >> 4, e = (tid & 15) * 4;
            float4 v = *reinterpret_cast<const float4*>(
                &X[(size_t)(b * LSEQ + sb + sl) * DM + h * ED + e]);
            Vs[sl][e] = v.x; Vs[sl][e + 1] = v.y; Vs[sl][e + 2] = v.z; Vs[sl][e + 3] = v.w;
        }
        __syncthreads();
        #pragma unroll
        for (int s = 0; s < 16; s++) {
            float a[4], bb[4];
            #pragma unroll
            for (int i = 0; i < 4; i++) a[i]  = As[ty * 4 + i][s];
            #pragma unroll
            for (int j = 0; j < 4; j++) bb[j] = Vs[s][tx * 4 + j];
            #pragma unroll
            for (int i = 0; i < 4; i++)
                #pragma unroll
                for (int j = 0; j < 4; j++)
                    acc[i][j] = fmaf(a[i], bb[j], acc[i][j]);
        }
        __syncthreads();
    }
    size_t rvb = (size_t)(b * NH + h) * RN * ED;
    #pragma unroll
    for (int i = 0; i < 4; i++)
        #pragma unroll
        for (int j = 0; j < 4; j++)
            atomicAdd(&g_rv[rvb + (size_t)(ty * 4 + i) * ED + tx * 4 + j], acc[i][j]);
}

// ---------- kernel 3: q-branch attention + epilogue ----------
__global__ __launch_bounds__(256) void qattn_kernel(
    const float* __restrict__ rp, float* __restrict__ out)
{
    int b = blockIdx.z, h = blockIdx.y;
    int l0 = blockIdx.x * 32;
    __shared__ float Rh[64][66];
    __shared__ float Qs[32][66];
    __shared__ float Ss[32][66];
    int tid = threadIdx.x;
    {
        int r = tid >> 2, e0 = (tid & 3) << 4;
        const float* src = rp + (size_t)r * DM + h * ED + e0;
        #pragma unroll
        for (int t = 0; t < 4; t++) {
            float4 v = *reinterpret_cast<const float4*>(src + 4 * t);
            Rh[r][e0 + 4*t] = v.x; Rh[r][e0 + 4*t + 1] = v.y;
            Rh[r][e0 + 4*t + 2] = v.z; Rh[r][e0 + 4*t + 3] = v.w;
        }
    }
    {
        int l = tid >> 3, e0 = (tid & 7) << 3;
        const float* src = g_q + (size_t)(b * LSEQ + l0 + l) * DM + h * ED + e0;
        #pragma unroll
        for (int t = 0; t < 2; t++) {
            float4 v = *reinterpret_cast<const float4*>(src + 4 * t);
            Qs[l][e0 + 4*t] = v.x; Qs[l][e0 + 4*t + 1] = v.y;
            Qs[l][e0 + 4*t + 2] = v.z; Qs[l][e0 + 4*t + 3] = v.w;
        }
    }
    __syncthreads();
    int ty = tid >> 4, tx = tid & 15;
    {
        float acc[2][4] = {};
        #pragma unroll 8
        for (int e = 0; e < 64; e++) {
            float a0 = Qs[ty * 2][e], a1 = Qs[ty * 2 + 1][e];
            float bb[4];
            #pragma unroll
            for (int j = 0; j < 4; j++) bb[j] = Rh[tx * 4 + j][e];
            #pragma unroll
            for (int j = 0; j < 4; j++) {
                acc[0][j] = fmaf(a0, bb[j], acc[0][j]);
                acc[1][j] = fmaf(a1, bb[j], acc[1][j]);
            }
        }
        #pragma unroll
        for (int i = 0; i < 2; i++)
            #pragma unroll
            for (int j = 0; j < 4; j++)
                Ss[ty * 2 + i][tx * 4 + j] = 0.125f * acc[i][j];
    }
    __syncthreads();
    {
        int l = tid >> 3, sub = tid & 7;
        int lt = l0 + l;
        float m = -1e30f;
        float v[8];
        #pragma unroll
        for (int t = 0; t < 8; t++) { v[t] = Ss[l][sub * 8 + t]; m = fmaxf(m, v[t]); }
        m = fmaxf(m, __shfl_xor_sync(~0u, m, 1));
        m = fmaxf(m, __shfl_xor_sync(~0u, m, 2));
        m = fmaxf(m, __shfl_xor_sync(~0u, m, 4));
        float zs = 0.0f;
        #pragma unroll
        for (int t = 0; t < 8; t++) { v[t] = expf(v[t] - m); zs += v[t]; }
        zs += __shfl_xor_sync(~0u, zs, 1);
        zs += __shfl_xor_sync(~0u, zs, 2);
        zs += __shfl_xor_sync(~0u, zs, 4);
        float inv = 1.0f / zs;
        #pragma unroll
        for (int t = 0; t < 8; t += 2) {
            int r = sub * 8 + t;
            int j = r >> 1;
            float c = g_cos[lt * 32 + j], sn = g_sin[lt * 32 + j];
            float a0 = v[t] * inv, a1 = v[t + 1] * inv;
            Ss[l][r]     = a0 * c - a1 * sn;
            Ss[l][r + 1] = a0 * sn + a1 * c;
        }
    }
    __syncthreads();
    {
        int r = tid >> 2, e0 = (tid & 3) << 4;
        const float* src = g_rv + (size_t)(b * NH + h) * RN * ED + (size_t)r * ED + e0;
        #pragma unroll
        for (int t = 0; t < 4; t++) {
            float4 v = *reinterpret_cast<const float4*>(src + 4 * t);
            Rh[r][e0 + 4*t] = v.x; Rh[r][e0 + 4*t + 1] = v.y;
            Rh[r][e0 + 4*t + 2] = v.z; Rh[r][e0 + 4*t + 3] = v.w;
        }
    }
    __syncthreads();
    {
        float acc[2][4] = {};
        #pragma unroll 8
        for (int r = 0; r < 64; r++) {
            float a0 = Ss[ty * 2][r], a1 = Ss[ty * 2 + 1][r];
            float bb[4];
            #pragma unroll
            for (int j = 0; j < 4; j++) bb[j] = Rh[r][tx * 4 + j];
            #pragma unroll
            for (int j = 0; j < 4; j++) {
                acc[0][j] = fmaf(a0, bb[j], acc[0][j]);
                acc[1][j] = fmaf(a1, bb[j], acc[1][j]);
            }
        }
        #pragma unroll
        for (int i = 0; i < 2; i++) {
            #pragma unroll
            for (int j = 0; j < 4; j++) {
                int l = ty * 2 + i, e = tx * 4 + j;
                size_t idx = (size_t)(b * LSEQ + l0 + l) * DM + h * ED + e;
                out[idx] = (acc[i][j] + g_skip[idx]) * g_z[idx];
            }
        }
    }
}

extern "C" void kernel_launch(void* const* d_in, const int* in_sizes, int n_in,
                              void* d_out, int out_size)
{
    const float* x     = (const float*)d_in[0];
    const float* Wq    = (const float*)d_in[1];
    const float* bq    = (const float*)d_in[2];
    const float* Wk    = (const float*)d_in[3];
    const float* bk    = (const float*)d_in[4];
    const float* Wskip = (const float*)d_in[5];
    const float* bskip = (const float*)d_in[6];
    const float* Wz    = (const float*)d_in[7];
    const float* bz    = (const float*)d_in[8];
    const float* rp    = (const float*)d_in[9];
    float* out = (float*)d_out;

    rope_table_kernel<<<(LSEQ * 32 + 255) / 256, 256>>>();
    gemm_big_tc_kernel<<<dim3(DM / 64, MTOT / 128, 4), 256>>>(
        x, Wq, bq, Wk, bk, Wskip, bskip, Wz, bz);
    router_scores_kernel<<<dim3(LSEQ / 64, NH, BSZ), 256>>>(rp);
    softmax_rows_kernel<<<BSZ * NH * RN, 256>>>();
    zero_rv_kernel<<<(BSZ * NH * RN * ED + 255) / 256, 256>>>();
    router_v_kernel<<<dim3(LSEQ / 256, NH, BSZ), 256>>>(x);
    qattn_kernel<<<dim3(LSEQ / 32, NH, BSZ), 256>>>(rp, out);
}